// round 12
// baseline (speedup 1.0000x reference)
#include <cuda_runtime.h>
#include <cuda_fp16.h>
#include <cstdint>

// Problem constants
#define B_    32
#define S_    256
#define D_    1024
#define H_    16
#define C_    64
#define MTOT  (B_ * S_)   // 8192

// Scratch (allocation-free rule: device globals)
__device__ __align__(16) __half g_qh[MTOT * D_];
__device__ __align__(16) __half g_kh[MTOT * D_];
__device__ __align__(16) __half g_vh[MTOT * D_];
__device__ __align__(16) __half g_xh[MTOT * D_];
__device__ __align__(16) __half g_wh[3 * D_ * D_];

// ---------------------------------------------------------------------------
__device__ __forceinline__ uint32_t smem_u32(const void* p) {
    uint32_t a;
    asm("{ .reg .u64 t; cvta.to.shared.u64 t, %1; cvt.u32.u64 %0, t; }" : "=r"(a) : "l"(p));
    return a;
}

__device__ __forceinline__ void cpa16(uint32_t dst, const void* src) {
    asm volatile("cp.async.cg.shared.global [%0], [%1], 16;" :: "r"(dst), "l"(src));
}

__device__ __forceinline__ void ldsm_x4(uint32_t* r, uint32_t addr) {
    asm volatile("ldmatrix.sync.aligned.m8n8.x4.shared.b16 {%0,%1,%2,%3}, [%4];"
                 : "=r"(r[0]), "=r"(r[1]), "=r"(r[2]), "=r"(r[3]) : "r"(addr));
}
__device__ __forceinline__ void ldsm_x4_t(uint32_t* r, uint32_t addr) {
    asm volatile("ldmatrix.sync.aligned.m8n8.x4.trans.shared.b16 {%0,%1,%2,%3}, [%4];"
                 : "=r"(r[0]), "=r"(r[1]), "=r"(r[2]), "=r"(r[3]) : "r"(addr));
}

__device__ __forceinline__ void mma16816(float* d, const uint32_t* a, const uint32_t* b) {
    asm volatile(
        "mma.sync.aligned.m16n8k16.row.col.f32.f16.f16.f32 "
        "{%0,%1,%2,%3}, {%4,%5,%6,%7}, {%8,%9}, {%0,%1,%2,%3};"
        : "+f"(d[0]), "+f"(d[1]), "+f"(d[2]), "+f"(d[3])
        : "r"(a[0]), "r"(a[1]), "r"(a[2]), "r"(a[3]), "r"(b[0]), "r"(b[1]));
}

__device__ __forceinline__ float ex2f(float x) {
    float r;
    asm("ex2.approx.f32 %0, %1;" : "=f"(r) : "f"(x));
    return r;
}
__device__ __forceinline__ float rcpf(float x) {
    float r;
    asm("rcp.approx.f32 %0, %1;" : "=f"(r) : "f"(x));
    return r;
}

// ---------------------------------------------------------------------------
// Kernel 0: fp32 -> fp16 conversions
// ---------------------------------------------------------------------------
__global__ __launch_bounds__(256)
void cvt_x(const float* __restrict__ src, __half* __restrict__ hi, int n4)
{
    int i = blockIdx.x * blockDim.x + threadIdx.x;
    if (i >= n4) return;
    float4 v = ((const float4*)src)[i];
    float a[4] = {v.x, v.y, v.z, v.w};
    __half h[4];
#pragma unroll
    for (int j = 0; j < 4; j++) h[j] = __float2half(a[j]);
    ((uint2*)hi)[i] = *(uint2*)h;
}

__global__ __launch_bounds__(256)
void cvt_w(const float* __restrict__ Wq, const float* __restrict__ Wk,
           const float* __restrict__ Wv, __half* __restrict__ hi)
{
    const int z = blockIdx.z;
    const float* src = (z == 0) ? Wq : (z == 1) ? Wk : Wv;
    const int n4 = D_ * D_ / 4;
    int i = blockIdx.x * blockDim.x + threadIdx.x;
    if (i >= n4) return;
    float4 v = ((const float4*)src)[i];
    float a[4] = {v.x, v.y, v.z, v.w};
    __half h[4];
#pragma unroll
    for (int j = 0; j < 4; j++) h[j] = __float2half(a[j]);
    ((uint2*)(hi + (long)z * D_ * D_))[i] = *(uint2*)h;
}

// ---------------------------------------------------------------------------
// Kernel 1: fp16 GEMM via mma.sync, f32 accumulators (R9 proven config),
// N-tile narrowed to 64 for wave-tail reduction (3072 CTAs: 10.38->11 waves,
// 94% util vs 86%). Block tile 128x64, BK=32, 256 threads (8 warps: 4M x 2N,
// warp tile 32x32), 2 CTAs/SM, double-buffered cp.async, padded stride 40.
// ---------------------------------------------------------------------------
#define GTM 128
#define GTN 64
#define GTK 32
#define NCHUNK (D_ / GTK)              // 32
#define LDT 40
#define TILE_A_BYTES (128 * LDT * 2)    // 10240 B
#define TILE_B_BYTES (64 * LDT * 2)     // 5120 B
#define STAGE_BYTES (TILE_A_BYTES + TILE_B_BYTES)  // 15360 B
#define GEMM_SMEM (2 * STAGE_BYTES)     // 30720 B

__device__ __forceinline__ void load_chunk(uint32_t buf,
    const __half* __restrict__ Ah, const __half* __restrict__ Bh,
    int k0, int tid)
{
#pragma unroll
    for (int i = 0; i < 3; i++) {
        int idx = tid + (i << 8);        // 0..767
        if (idx < 512) {                 // A: 128 rows x 4 segs
            int row = idx >> 2;
            int seg = idx & 3;
            uint32_t so = (uint32_t)(row * (LDT * 2) + seg * 16);
            cpa16(buf + so, Ah + (long)row * D_ + k0 + seg * 8);
        } else {                          // B: 64 rows x 4 segs
            int j = idx - 512;
            int row = j >> 2;
            int seg = j & 3;
            uint32_t so = (uint32_t)(row * (LDT * 2) + seg * 16);
            cpa16(buf + TILE_A_BYTES + so, Bh + (long)row * D_ + k0 + seg * 8);
        }
    }
}

__global__ __launch_bounds__(256, 2)
void qkv_tc()
{
    extern __shared__ char smem[];
    const uint32_t sb = smem_u32(smem);
    const int tid = threadIdx.x;
    const int wid = tid >> 5;
    const int lid = tid & 31;

    const int n0 = blockIdx.x * GTN;
    const int m0 = blockIdx.y * GTM;
    const int z  = blockIdx.z;

    const __half* Ah = g_xh + (long)m0 * D_;
    const __half* Bh = g_wh + (long)z * D_ * D_ + (long)n0 * D_;
    __half* O = (z == 0) ? g_qh : (z == 1) ? g_kh : g_vh;

    const int warp_m = (wid & 3) * 32;    // 4 warps along M
    const int warp_n = (wid >> 2) * 32;   // 2 warps along N (32 each)

    const int a_row = ((lid >> 3) & 1) * 8 + (lid & 7);
    const int a_col = (lid >> 4) * 8;
    const int mi    = lid >> 3;
    const int b_row = (mi >> 1) * 8 + (lid & 7);
    const int b_col = (mi & 1) * 8;

    float acc[2][4][4];
#pragma unroll
    for (int mt = 0; mt < 2; mt++)
#pragma unroll
        for (int nt = 0; nt < 4; nt++)
#pragma unroll
            for (int r = 0; r < 4; r++) acc[mt][nt][r] = 0.f;

    load_chunk(sb, Ah, Bh, 0, tid);
    asm volatile("cp.async.commit_group;" ::: "memory");

#pragma unroll 1
    for (int c = 0; c < NCHUNK; c++) {
        asm volatile("cp.async.wait_group 0;" ::: "memory");
        __syncthreads();

        if (c + 1 < NCHUNK) {
            load_chunk(sb + ((c + 1) & 1) * STAGE_BYTES, Ah, Bh,
                       (c + 1) * GTK, tid);
            asm volatile("cp.async.commit_group;" ::: "memory");
        }

        const uint32_t st = sb + (c & 1) * STAGE_BYTES;
        const uint32_t tAh = st;
        const uint32_t tBh = st + TILE_A_BYTES;

#pragma unroll
        for (int ks = 0; ks < 2; ks++) {
            const int kc = ks * 16;
            uint32_t ah[2][4];
#pragma unroll
            for (int mt = 0; mt < 2; mt++) {
                const uint32_t off =
                    (uint32_t)((warp_m + mt * 16 + a_row) * LDT + kc + a_col) * 2;
                ldsm_x4(ah[mt], tAh + off);
            }
#pragma unroll
            for (int p = 0; p < 2; p++) {
                const uint32_t off =
                    (uint32_t)((warp_n + p * 16 + b_row) * LDT + kc + b_col) * 2;
                uint32_t bh[4];
                ldsm_x4(bh, tBh + off);
#pragma unroll
                for (int half = 0; half < 2; half++)
#pragma unroll
                    for (int mt = 0; mt < 2; mt++)
                        mma16816(acc[mt][p * 2 + half], ah[mt], &bh[half * 2]);
            }
        }
        __syncthreads();
    }

    // Epilogue: fp16 stores
    const int er = lid >> 2;
    const int ec = (lid & 3) * 2;
#pragma unroll
    for (int mt = 0; mt < 2; mt++)
#pragma unroll
        for (int nt = 0; nt < 4; nt++) {
            const int row = m0 + warp_m + mt * 16 + er;
            const int col = n0 + warp_n + nt * 8 + ec;
            __half2 h01 = __floats2half2_rn(acc[mt][nt][0], acc[mt][nt][1]);
            __half2 h23 = __floats2half2_rn(acc[mt][nt][2], acc[mt][nt][3]);
            *(__half2*)(O + (long)row * D_ + col) = h01;
            *(__half2*)(O + (long)(row + 8) * D_ + col) = h23;
        }
}

// ---------------------------------------------------------------------------
// Kernel 2: tensor-core attention per (chunk c, batch b). Same math as R9;
// reg cap 64 (launch_bounds minBlocks=4) to lift occupancy 34% -> ~50%.
// ---------------------------------------------------------------------------
#define ASTRIDE 24   // halves; 48B padded row
__global__ __launch_bounds__(256, 4)
void attn(const float* __restrict__ mask, float* __restrict__ out)
{
    __shared__ __half q_s[S_][ASTRIDE];
    __shared__ __half k_s[S_][ASTRIDE];
    __shared__ __half v_s[S_][ASTRIDE];
    __shared__ float bias_s[S_];
    __shared__ float qsc_s[S_];

    const int c = blockIdx.x;
    const int b = blockIdx.y;
    const int t = threadIdx.x;
    const int wid = t >> 5;
    const int lane = t & 31;

    {
        const long gbase = (long)(b * S_ + t) * D_ + c * H_;
        const uint4* gq = (const uint4*)(g_qh + gbase);
        const uint4* gk = (const uint4*)(g_kh + gbase);
        const uint4* gv = (const uint4*)(g_vh + gbase);
        *(uint4*)&q_s[t][0] = gq[0];
        *(uint4*)&q_s[t][8] = gq[1];
        *(uint4*)&k_s[t][0] = gk[0];
        *(uint4*)&k_s[t][8] = gk[1];
        *(uint4*)&v_s[t][0] = gv[0];
        *(uint4*)&v_s[t][8] = gv[1];
        const float mv = mask[b * S_ + t];
        bias_s[t] = (mv > 0.f) ? 0.f : -100.f;
        qsc_s[t]  = (mv > 0.f) ? 0.045084234f : 0.f;   // log2(e)/32
    }
    __syncthreads();

    const uint32_t sq = smem_u32(q_s);
    const uint32_t sk = smem_u32(k_s);
    const uint32_t sv = smem_u32(v_s);

    const int m0 = wid * 32;

    const int a_row = lane & 15;
    const int a_coloff = (lane >> 4) * 16;
    uint32_t aq[2][4];
#pragma unroll
    for (int mt = 0; mt < 2; mt++)
        ldsm_x4(aq[mt], sq + (uint32_t)(m0 + mt * 16 + a_row) * 48 + a_coloff);

    const int r = lane >> 2;
    float sc0[2], sc1[2];
#pragma unroll
    for (int mt = 0; mt < 2; mt++) {
        sc0[mt] = qsc_s[m0 + mt * 16 + r];
        sc1[mt] = qsc_s[m0 + mt * 16 + 8 + r];
    }

    const int kb_row = ((lane >> 4) & 1) * 8 + (lane & 7);
    const int kb_coloff = ((lane >> 3) & 1) * 16;
    const int vb_row = (lane & 7) + ((lane >> 3) & 1) * 8;
    const int vb_coloff = (lane >> 4) * 16;

    float oacc[2][2][4];
#pragma unroll
    for (int mt = 0; mt < 2; mt++)
#pragma unroll
        for (int nt = 0; nt < 2; nt++)
#pragma unroll
            for (int i = 0; i < 4; i++) oacc[mt][nt][i] = 0.f;
    float sumA[2] = {0.f, 0.f}, sumB[2] = {0.f, 0.f};

#pragma unroll 1
    for (int ch = 0; ch < 8; ch++) {
        const int K0 = ch * 32;

        float cf[2][4][4];
#pragma unroll
        for (int mt = 0; mt < 2; mt++)
#pragma unroll
            for (int nt = 0; nt < 4; nt++)
#pragma unroll
                for (int i = 0; i < 4; i++) cf[mt][nt][i] = 0.f;

#pragma unroll
        for (int p = 0; p < 2; p++) {
            uint32_t bk[4];
            ldsm_x4(bk, sk + (uint32_t)(K0 + p * 16 + kb_row) * 48 + kb_coloff);
#pragma unroll
            for (int mt = 0; mt < 2; mt++) {
                mma16816(cf[mt][p * 2 + 0], aq[mt], &bk[0]);
                mma16816(cf[mt][p * 2 + 1], aq[mt], &bk[2]);
            }
        }

        uint32_t aw[2][2][4];
#pragma unroll
        for (int nt = 0; nt < 4; nt++) {
            const int col = K0 + nt * 8 + (lane & 3) * 2;
            const float bi0 = bias_s[col];
            const float bi1 = bias_s[col + 1];
            const int ks = nt >> 1;
            const int hi = (nt & 1) * 2;
#pragma unroll
            for (int mt = 0; mt < 2; mt++) {
                const float w0 = ex2f(fmaf(cf[mt][nt][0], sc0[mt], bi0));
                const float w1 = ex2f(fmaf(cf[mt][nt][1], sc0[mt], bi1));
                const float w2 = ex2f(fmaf(cf[mt][nt][2], sc1[mt], bi0));
                const float w3 = ex2f(fmaf(cf[mt][nt][3], sc1[mt], bi1));
                sumA[mt] += w0 + w1;
                sumB[mt] += w2 + w3;
                __half2 p01 = __floats2half2_rn(w0, w1);
                __half2 p23 = __floats2half2_rn(w2, w3);
                aw[mt][ks][hi + 0] = *(uint32_t*)&p01;
                aw[mt][ks][hi + 1] = *(uint32_t*)&p23;
            }
        }

#pragma unroll
        for (int ks = 0; ks < 2; ks++) {
            uint32_t bv[4];
            ldsm_x4_t(bv, sv + (uint32_t)(K0 + ks * 16 + vb_row) * 48 + vb_coloff);
#pragma unroll
            for (int mt = 0; mt < 2; mt++) {
                mma16816(oacc[mt][0], aw[mt][ks], &bv[0]);
                mma16816(oacc[mt][1], aw[mt][ks], &bv[2]);
            }
        }
    }

#pragma unroll
    for (int mt = 0; mt < 2; mt++) {
        sumA[mt] += __shfl_xor_sync(0xffffffffu, sumA[mt], 1);
        sumA[mt] += __shfl_xor_sync(0xffffffffu, sumA[mt], 2);
        sumB[mt] += __shfl_xor_sync(0xffffffffu, sumB[mt], 1);
        sumB[mt] += __shfl_xor_sync(0xffffffffu, sumB[mt], 2);
    }
    const float invA0 = rcpf(sumA[0]), invB0 = rcpf(sumB[0]);
    const float invA1 = rcpf(sumA[1]), invB1 = rcpf(sumB[1]);

    const long obase = (long)(b * S_) * D_ + c * H_;
#pragma unroll
    for (int mt = 0; mt < 2; mt++) {
        const float iA = mt ? invA1 : invA0;
        const float iB = mt ? invB1 : invB0;
#pragma unroll
        for (int nt = 0; nt < 2; nt++) {
            const int row = m0 + mt * 16 + r;
            const int col = nt * 8 + (lane & 3) * 2;
            float* p0 = out + obase + (long)row * D_ + col;
            float* p1 = p0 + 8 * D_;
            *(float2*)p0 = make_float2(oacc[mt][nt][0] * iA, oacc[mt][nt][1] * iA);
            *(float2*)p1 = make_float2(oacc[mt][nt][2] * iB, oacc[mt][nt][3] * iB);
        }
    }
}

// ---------------------------------------------------------------------------
extern "C" void kernel_launch(void* const* d_in, const int* in_sizes, int n_in,
                              void* d_out, int out_size)
{
    const float* x    = (const float*)d_in[0];
    const float* mask = (const float*)d_in[1];
    const float* Wq   = (const float*)d_in[2];
    const float* Wk   = (const float*)d_in[3];
    const float* Wv   = (const float*)d_in[4];
    float* out = (float*)d_out;

    __half *xh, *wh;
    cudaGetSymbolAddress((void**)&xh, g_xh);
    cudaGetSymbolAddress((void**)&wh, g_wh);

    cvt_x<<<(MTOT * D_ / 4 + 255) / 256, 256>>>(x, xh, MTOT * D_ / 4);
    dim3 gw((D_ * D_ / 4 + 255) / 256, 1, 3);
    cvt_w<<<gw, 256>>>(Wq, Wk, Wv, wh);

    static bool attr_set = false;
    if (!attr_set) {
        cudaFuncSetAttribute(qkv_tc, cudaFuncAttributeMaxDynamicSharedMemorySize, GEMM_SMEM);
        attr_set = true;
    }

    dim3 g1(D_ / GTN, MTOT / GTM, 3);
    qkv_tc<<<g1, 256, GEMM_SMEM>>>();

    dim3 g2(C_, B_);
    attn<<<g2, 256>>>(mask, out);
}

// round 16
// speedup vs baseline: 1.3813x; 1.3813x over previous
#include <cuda_runtime.h>
#include <cuda_fp16.h>
#include <cstdint>

// Problem constants
#define B_    32
#define S_    256
#define D_    1024
#define H_    16
#define C_    64
#define MTOT  (B_ * S_)   // 8192

// Scratch (allocation-free rule: device globals)
__device__ __align__(16) __half g_qh[MTOT * D_];
__device__ __align__(16) __half g_kh[MTOT * D_];
__device__ __align__(16) __half g_vh[MTOT * D_];
__device__ __align__(16) __half g_xh[MTOT * D_];
__device__ __align__(16) __half g_wh[3 * D_ * D_];

// ---------------------------------------------------------------------------
__device__ __forceinline__ uint32_t smem_u32(const void* p) {
    uint32_t a;
    asm("{ .reg .u64 t; cvta.to.shared.u64 t, %1; cvt.u32.u64 %0, t; }" : "=r"(a) : "l"(p));
    return a;
}

__device__ __forceinline__ void cpa16(uint32_t dst, const void* src) {
    asm volatile("cp.async.cg.shared.global [%0], [%1], 16;" :: "r"(dst), "l"(src));
}

__device__ __forceinline__ void ldsm_x4(uint32_t* r, uint32_t addr) {
    asm volatile("ldmatrix.sync.aligned.m8n8.x4.shared.b16 {%0,%1,%2,%3}, [%4];"
                 : "=r"(r[0]), "=r"(r[1]), "=r"(r[2]), "=r"(r[3]) : "r"(addr));
}
__device__ __forceinline__ void ldsm_x4_t(uint32_t* r, uint32_t addr) {
    asm volatile("ldmatrix.sync.aligned.m8n8.x4.trans.shared.b16 {%0,%1,%2,%3}, [%4];"
                 : "=r"(r[0]), "=r"(r[1]), "=r"(r[2]), "=r"(r[3]) : "r"(addr));
}

__device__ __forceinline__ void mma16816(float* d, const uint32_t* a, const uint32_t* b) {
    asm volatile(
        "mma.sync.aligned.m16n8k16.row.col.f32.f16.f16.f32 "
        "{%0,%1,%2,%3}, {%4,%5,%6,%7}, {%8,%9}, {%0,%1,%2,%3};"
        : "+f"(d[0]), "+f"(d[1]), "+f"(d[2]), "+f"(d[3])
        : "r"(a[0]), "r"(a[1]), "r"(a[2]), "r"(a[3]), "r"(b[0]), "r"(b[1]));
}

__device__ __forceinline__ float ex2f(float x) {
    float r;
    asm("ex2.approx.f32 %0, %1;" : "=f"(r) : "f"(x));
    return r;
}
__device__ __forceinline__ float rcpf(float x) {
    float r;
    asm("rcp.approx.f32 %0, %1;" : "=f"(r) : "f"(x));
    return r;
}

// ---------------------------------------------------------------------------
// Kernel 0: fp32 -> fp16 conversions
// ---------------------------------------------------------------------------
__global__ __launch_bounds__(256)
void cvt_x(const float* __restrict__ src, __half* __restrict__ hi, int n4)
{
    int i = blockIdx.x * blockDim.x + threadIdx.x;
    if (i >= n4) return;
    float4 v = ((const float4*)src)[i];
    float a[4] = {v.x, v.y, v.z, v.w};
    __half h[4];
#pragma unroll
    for (int j = 0; j < 4; j++) h[j] = __float2half(a[j]);
    ((uint2*)hi)[i] = *(uint2*)h;
}

__global__ __launch_bounds__(256)
void cvt_w(const float* __restrict__ Wq, const float* __restrict__ Wk,
           const float* __restrict__ Wv, __half* __restrict__ hi)
{
    const int z = blockIdx.z;
    const float* src = (z == 0) ? Wq : (z == 1) ? Wk : Wv;
    const int n4 = D_ * D_ / 4;
    int i = blockIdx.x * blockDim.x + threadIdx.x;
    if (i >= n4) return;
    float4 v = ((const float4*)src)[i];
    float a[4] = {v.x, v.y, v.z, v.w};
    __half h[4];
#pragma unroll
    for (int j = 0; j < 4; j++) h[j] = __float2half(a[j]);
    ((uint2*)(hi + (long)z * D_ * D_))[i] = *(uint2*)h;
}

// ---------------------------------------------------------------------------
// Kernel 1: fp16 GEMM via mma.sync, f32 accumulators. R9 proven shape
// (128x128 tile, 256 threads, 8 warps 4Mx2N, warp tile 32x64, 2 CTAs/SM)
// with BK=64 (16 chunks) and a SINGLE barrier per chunk (bottom sync removed
// -- the next iteration's top sync orders buffer reuse).
// ---------------------------------------------------------------------------
#define GTM 128
#define GTN 128
#define GTK 64
#define NCHUNK (D_ / GTK)              // 16
#define LDT 72                          // 64 halves + pad; 144B row stride
#define TILE_BYTES (128 * LDT * 2)      // 18432 B
#define STAGE_BYTES (2 * TILE_BYTES)    // A + B = 36864 B
#define GEMM_SMEM (2 * STAGE_BYTES)     // 73728 B

__device__ __forceinline__ void load_chunk(uint32_t buf,
    const __half* __restrict__ Ah, const __half* __restrict__ Bh,
    int k0, int tid)
{
#pragma unroll
    for (int i = 0; i < 8; i++) {
        int idx = tid + (i << 8);          // 0..2047
        int j   = idx & 1023;
        int row = j >> 3;                  // 0..127
        int seg = j & 7;                   // 16B segments of 128B row
        uint32_t so = (uint32_t)(row * (LDT * 2) + seg * 16);
        long go = (long)row * D_ + k0 + seg * 8;
        if (idx < 1024) cpa16(buf + so,              Ah + go);
        else            cpa16(buf + TILE_BYTES + so, Bh + go);
    }
}

__global__ __launch_bounds__(256, 2)
void qkv_tc()
{
    extern __shared__ char smem[];
    const uint32_t sb = smem_u32(smem);
    const int tid = threadIdx.x;
    const int wid = tid >> 5;
    const int lid = tid & 31;

    const int n0 = blockIdx.x * GTN;
    const int m0 = blockIdx.y * GTM;
    const int z  = blockIdx.z;

    const __half* Ah = g_xh + (long)m0 * D_;
    const __half* Bh = g_wh + (long)z * D_ * D_ + (long)n0 * D_;
    __half* O = (z == 0) ? g_qh : (z == 1) ? g_kh : g_vh;

    const int warp_m = (wid & 3) * 32;    // 4 warps along M
    const int warp_n = (wid >> 2) * 64;   // 2 warps along N

    const int a_row = ((lid >> 3) & 1) * 8 + (lid & 7);
    const int a_col = (lid >> 4) * 8;
    const int mi    = lid >> 3;
    const int b_row = (mi >> 1) * 8 + (lid & 7);
    const int b_col = (mi & 1) * 8;

    float acc[2][8][4];
#pragma unroll
    for (int mt = 0; mt < 2; mt++)
#pragma unroll
        for (int nt = 0; nt < 8; nt++)
#pragma unroll
            for (int r = 0; r < 4; r++) acc[mt][nt][r] = 0.f;

    load_chunk(sb, Ah, Bh, 0, tid);
    asm volatile("cp.async.commit_group;" ::: "memory");

#pragma unroll 1
    for (int c = 0; c < NCHUNK; c++) {
        asm volatile("cp.async.wait_group 0;" ::: "memory");
        __syncthreads();   // load(c) visible; all warps done reading buf((c+1)&1)

        if (c + 1 < NCHUNK) {
            load_chunk(sb + ((c + 1) & 1) * STAGE_BYTES, Ah, Bh,
                       (c + 1) * GTK, tid);
            asm volatile("cp.async.commit_group;" ::: "memory");
        }

        const uint32_t st = sb + (c & 1) * STAGE_BYTES;
        const uint32_t tAh = st;
        const uint32_t tBh = st + TILE_BYTES;

#pragma unroll
        for (int ks = 0; ks < 4; ks++) {
            const int kc = ks * 16;
            uint32_t ah[2][4];
#pragma unroll
            for (int mt = 0; mt < 2; mt++) {
                const uint32_t off =
                    (uint32_t)((warp_m + mt * 16 + a_row) * LDT + kc + a_col) * 2;
                ldsm_x4(ah[mt], tAh + off);
            }
#pragma unroll
            for (int p = 0; p < 4; p++) {
                const uint32_t off =
                    (uint32_t)((warp_n + p * 16 + b_row) * LDT + kc + b_col) * 2;
                uint32_t bh[4];
                ldsm_x4(bh, tBh + off);
#pragma unroll
                for (int half = 0; half < 2; half++)
#pragma unroll
                    for (int mt = 0; mt < 2; mt++)
                        mma16816(acc[mt][p * 2 + half], ah[mt], &bh[half * 2]);
            }
        }
        // no bottom sync: next iteration's top sync orders buffer reuse
    }

    // Epilogue: fp16 stores
    const int er = lid >> 2;
    const int ec = (lid & 3) * 2;
#pragma unroll
    for (int mt = 0; mt < 2; mt++)
#pragma unroll
        for (int nt = 0; nt < 8; nt++) {
            const int row = m0 + warp_m + mt * 16 + er;
            const int col = n0 + warp_n + nt * 8 + ec;
            __half2 h01 = __floats2half2_rn(acc[mt][nt][0], acc[mt][nt][1]);
            __half2 h23 = __floats2half2_rn(acc[mt][nt][2], acc[mt][nt][3]);
            *(__half2*)(O + (long)row * D_ + col) = h01;
            *(__half2*)(O + (long)(row + 8) * D_ + col) = h23;
        }
}

// ---------------------------------------------------------------------------
// Kernel 2: tensor-core attention per (chunk c, batch b). Exact R9 config
// (known-good 46.5us; no reg cap).
// ---------------------------------------------------------------------------
#define ASTRIDE 24   // halves; 48B padded row
__global__ __launch_bounds__(256)
void attn(const float* __restrict__ mask, float* __restrict__ out)
{
    __shared__ __half q_s[S_][ASTRIDE];
    __shared__ __half k_s[S_][ASTRIDE];
    __shared__ __half v_s[S_][ASTRIDE];
    __shared__ float bias_s[S_];
    __shared__ float qsc_s[S_];

    const int c = blockIdx.x;
    const int b = blockIdx.y;
    const int t = threadIdx.x;
    const int wid = t >> 5;
    const int lane = t & 31;

    {
        const long gbase = (long)(b * S_ + t) * D_ + c * H_;
        const uint4* gq = (const uint4*)(g_qh + gbase);
        const uint4* gk = (const uint4*)(g_kh + gbase);
        const uint4* gv = (const uint4*)(g_vh + gbase);
        *(uint4*)&q_s[t][0] = gq[0];
        *(uint4*)&q_s[t][8] = gq[1];
        *(uint4*)&k_s[t][0] = gk[0];
        *(uint4*)&k_s[t][8] = gk[1];
        *(uint4*)&v_s[t][0] = gv[0];
        *(uint4*)&v_s[t][8] = gv[1];
        const float mv = mask[b * S_ + t];
        bias_s[t] = (mv > 0.f) ? 0.f : -100.f;
        qsc_s[t]  = (mv > 0.f) ? 0.045084234f : 0.f;   // log2(e)/32
    }
    __syncthreads();

    const uint32_t sq = smem_u32(q_s);
    const uint32_t sk = smem_u32(k_s);
    const uint32_t sv = smem_u32(v_s);

    const int m0 = wid * 32;

    const int a_row = lane & 15;
    const int a_coloff = (lane >> 4) * 16;
    uint32_t aq[2][4];
#pragma unroll
    for (int mt = 0; mt < 2; mt++)
        ldsm_x4(aq[mt], sq + (uint32_t)(m0 + mt * 16 + a_row) * 48 + a_coloff);

    const int r = lane >> 2;
    float sc0[2], sc1[2];
#pragma unroll
    for (int mt = 0; mt < 2; mt++) {
        sc0[mt] = qsc_s[m0 + mt * 16 + r];
        sc1[mt] = qsc_s[m0 + mt * 16 + 8 + r];
    }

    const int kb_row = ((lane >> 4) & 1) * 8 + (lane & 7);
    const int kb_coloff = ((lane >> 3) & 1) * 16;
    const int vb_row = (lane & 7) + ((lane >> 3) & 1) * 8;
    const int vb_coloff = (lane >> 4) * 16;

    float oacc[2][2][4];
#pragma unroll
    for (int mt = 0; mt < 2; mt++)
#pragma unroll
        for (int nt = 0; nt < 2; nt++)
#pragma unroll
            for (int i = 0; i < 4; i++) oacc[mt][nt][i] = 0.f;
    float sumA[2] = {0.f, 0.f}, sumB[2] = {0.f, 0.f};

#pragma unroll 1
    for (int ch = 0; ch < 8; ch++) {
        const int K0 = ch * 32;

        float cf[2][4][4];
#pragma unroll
        for (int mt = 0; mt < 2; mt++)
#pragma unroll
            for (int nt = 0; nt < 4; nt++)
#pragma unroll
                for (int i = 0; i < 4; i++) cf[mt][nt][i] = 0.f;

#pragma unroll
        for (int p = 0; p < 2; p++) {
            uint32_t bk[4];
            ldsm_x4(bk, sk + (uint32_t)(K0 + p * 16 + kb_row) * 48 + kb_coloff);
#pragma unroll
            for (int mt = 0; mt < 2; mt++) {
                mma16816(cf[mt][p * 2 + 0], aq[mt], &bk[0]);
                mma16816(cf[mt][p * 2 + 1], aq[mt], &bk[2]);
            }
        }

        uint32_t aw[2][2][4];
#pragma unroll
        for (int nt = 0; nt < 4; nt++) {
            const int col = K0 + nt * 8 + (lane & 3) * 2;
            const float bi0 = bias_s[col];
            const float bi1 = bias_s[col + 1];
            const int ks = nt >> 1;
            const int hi = (nt & 1) * 2;
#pragma unroll
            for (int mt = 0; mt < 2; mt++) {
                const float w0 = ex2f(fmaf(cf[mt][nt][0], sc0[mt], bi0));
                const float w1 = ex2f(fmaf(cf[mt][nt][1], sc0[mt], bi1));
                const float w2 = ex2f(fmaf(cf[mt][nt][2], sc1[mt], bi0));
                const float w3 = ex2f(fmaf(cf[mt][nt][3], sc1[mt], bi1));
                sumA[mt] += w0 + w1;
                sumB[mt] += w2 + w3;
                __half2 p01 = __floats2half2_rn(w0, w1);
                __half2 p23 = __floats2half2_rn(w2, w3);
                aw[mt][ks][hi + 0] = *(uint32_t*)&p01;
                aw[mt][ks][hi + 1] = *(uint32_t*)&p23;
            }
        }

#pragma unroll
        for (int ks = 0; ks < 2; ks++) {
            uint32_t bv[4];
            ldsm_x4_t(bv, sv + (uint32_t)(K0 + ks * 16 + vb_row) * 48 + vb_coloff);
#pragma unroll
            for (int mt = 0; mt < 2; mt++) {
                mma16816(oacc[mt][0], aw[mt][ks], &bv[0]);
                mma16816(oacc[mt][1], aw[mt][ks], &bv[2]);
            }
        }
    }

#pragma unroll
    for (int mt = 0; mt < 2; mt++) {
        sumA[mt] += __shfl_xor_sync(0xffffffffu, sumA[mt], 1);
        sumA[mt] += __shfl_xor_sync(0xffffffffu, sumA[mt], 2);
        sumB[mt] += __shfl_xor_sync(0xffffffffu, sumB[mt], 1);
        sumB[mt] += __shfl_xor_sync(0xffffffffu, sumB[mt], 2);
    }
    const float invA0 = rcpf(sumA[0]), invB0 = rcpf(sumB[0]);
    const float invA1 = rcpf(sumA[1]), invB1 = rcpf(sumB[1]);

    const long obase = (long)(b * S_) * D_ + c * H_;
#pragma unroll
    for (int mt = 0; mt < 2; mt++) {
        const float iA = mt ? invA1 : invA0;
        const float iB = mt ? invB1 : invB0;
#pragma unroll
        for (int nt = 0; nt < 2; nt++) {
            const int row = m0 + mt * 16 + r;
            const int col = nt * 8 + (lane & 3) * 2;
            float* p0 = out + obase + (long)row * D_ + col;
            float* p1 = p0 + 8 * D_;
            *(float2*)p0 = make_float2(oacc[mt][nt][0] * iA, oacc[mt][nt][1] * iA);
            *(float2*)p1 = make_float2(oacc[mt][nt][2] * iB, oacc[mt][nt][3] * iB);
        }
    }
}

// ---------------------------------------------------------------------------
extern "C" void kernel_launch(void* const* d_in, const int* in_sizes, int n_in,
                              void* d_out, int out_size)
{
    const float* x    = (const float*)d_in[0];
    const float* mask = (const float*)d_in[1];
    const float* Wq   = (const float*)d_in[2];
    const float* Wk   = (const float*)d_in[3];
    const float* Wv   = (const float*)d_in[4];
    float* out = (float*)d_out;

    __half *xh, *wh;
    cudaGetSymbolAddress((void**)&xh, g_xh);
    cudaGetSymbolAddress((void**)&wh, g_wh);

    cvt_x<<<(MTOT * D_ / 4 + 255) / 256, 256>>>(x, xh, MTOT * D_ / 4);
    dim3 gw((D_ * D_ / 4 + 255) / 256, 1, 3);
    cvt_w<<<gw, 256>>>(Wq, Wk, Wv, wh);

    static bool attr_set = false;
    if (!attr_set) {
        cudaFuncSetAttribute(qkv_tc, cudaFuncAttributeMaxDynamicSharedMemorySize, GEMM_SMEM);
        attr_set = true;
    }

    dim3 g1(D_ / GTN, MTOT / GTM, 3);
    qkv_tc<<<g1, 256, GEMM_SMEM>>>();

    dim3 g2(C_, B_);
    attn<<<g2, 256>>>(mask, out);
}